// round 15
// baseline (speedup 1.0000x reference)
#include <cuda_runtime.h>
#include <cuda_fp16.h>
#include <cstdint>

#define N_NODES 50000
#define NPAD    50048
#define D_EMB   64
#define N_BATCH 64
#define PB      64    // pool partial blocks
#define UH_NODES 64   // nodes per update_h block
#define AST     136   // smem row stride in halves (272B = 17 uint4)

// ---------------- scratch (device globals; no allocation) ----------------
__device__ __half g_hh0[NPAD * D_EMB];          // fp16 h, triple-buffered
__device__ __half g_hh1[NPAD * D_EMB];
__device__ __half g_hh2[NPAD * D_EMB];
__device__ __half g_hnv[NPAD * D_EMB];          // fp16 spmm output
__device__ float  g_hsA[N_BATCH * D_EMB];
__device__ float  g_hsB[N_BATCH * D_EMB];
__device__ float  g_Wa[D_EMB * D_EMB];
__device__ float  g_Wb[D_EMB * D_EMB];
__device__ __half g_Wt[D_EMB * 2 * D_EMB];      // fused weights, [n=64][k=128] fp16
__device__ int    g_rowptr[N_NODES + 1];
__device__ float  g_pp[PB * N_BATCH * D_EMB];
__device__ int    g_bflag;                      // batch pool release flag

// ---------------- packed f32x2 helpers ------------------------------------
union F2U { float2 f; unsigned long long u; };
__device__ __forceinline__ void ffma2(float2& c, float2 a, float2 b) {
    F2U A, B, C; A.f = a; B.f = b; C.f = c;
    asm("fma.rn.f32x2 %0, %1, %2, %0;" : "+l"(C.u) : "l"(A.u), "l"(B.u));
    c = C.f;
}
__device__ __forceinline__ void fadd2(unsigned long long& acc, float2 v) {
    F2U V; V.f = v;
    asm("add.rn.f32x2 %0, %0, %1;" : "+l"(acc) : "l"(V.u));
}

__device__ __forceinline__ uint32_t s2u(const void* p) {
    return (uint32_t)__cvta_generic_to_shared(p);
}

#define MMA16816(c0, c1, c2, c3, a0, a1, a2, a3, b0, b1)                       \
    asm volatile(                                                              \
        "mma.sync.aligned.m16n8k16.row.col.f32.f16.f16.f32 "                   \
        "{%0,%1,%2,%3}, {%4,%5,%6,%7}, {%8,%9}, {%0,%1,%2,%3};"                \
        : "+f"(c0), "+f"(c1), "+f"(c2), "+f"(c3)                               \
        : "r"(a0), "r"(a1), "r"(a2), "r"(a3), "r"(b0), "r"(b1))

// ---------------- prep: fuse_w + init_h + init_hs + rowptr, one launch ----
#define INIT_BLKS ((N_NODES + 7) / 8)   // warp per node, 8 warps/block

__global__ void prep(const int* __restrict__ er, int nE,
                     const float* __restrict__ X, const float* __restrict__ Xs,
                     const float* __restrict__ W1, const float* __restrict__ W2,
                     const float* __restrict__ W3, const float* __restrict__ Wl,
                     __half* __restrict__ hh, float* __restrict__ hs) {
    __shared__ float sWl[8192];   // full Wl [128,64], 32 KB (block 0 only)
    int b = blockIdx.x, t = threadIdx.x;
    if (b == 0) {
        for (int i = t; i < 2048; i += 256)
            ((float4*)sWl)[i] = ((const float4*)Wl)[i];
        __syncthreads();
        for (int o = t; o < 4096; o += 256) {
            int i = o >> 6, j = o & 63;   // i = input dim (k), j = output dim (n)
            float sa = 0.f, sb = 0.f;
            #pragma unroll 8
            for (int k = 0; k < 64; k++) {
                sa = fmaf(W2[i * 64 + k], sWl[k * 64 + j], sa);
                sb = fmaf(W3[i * 64 + k], sWl[(64 + k) * 64 + j], sb);
            }
            g_Wa[o] = sa; g_Wb[o] = sb;
            g_Wt[j * 128 + i]      = __float2half(sa);   // Wt[n][k]      (h part)
            g_Wt[j * 128 + 64 + i] = __float2half(sb);   // Wt[n][64+k]   (hnv part)
        }
    } else if (b == 1) {
        if (t == 64) g_bflag = 0;    // reset batch flag each launch (graph replay)
        if (t < N_BATCH) {
            float x0 = Xs[t * 2], x1 = Xs[t * 2 + 1];
            float s = 0.f;
            #pragma unroll
            for (int j = 0; j < 64; j++) {
                float v = fmaxf(fmaf(x0, W1[j], x1 * W1[64 + j]), 0.f);
                s = fmaf(v, v, s);
            }
            float inv = 1.f / fmaxf(sqrtf(s), 1e-12f);
            #pragma unroll
            for (int j = 0; j < 64; j++) {
                float v = fmaxf(fmaf(x0, W1[j], x1 * W1[64 + j]), 0.f);
                hs[t * 64 + j] = v * inv;
            }
        }
    } else if (b < 2 + INIT_BLKS) {
        // warp per node, lanes own dims (2l, 2l+1); coalesced half2 stores
        int wid = t >> 5, l = t & 31;
        int n = (b - 2) * 8 + wid;
        if (n < N_NODES) {
            float x0 = X[n * 2], x1 = X[n * 2 + 1];
            float v0 = fmaxf(fmaf(x0, W1[2 * l],     x1 * W1[64 + 2 * l]),     0.f);
            float v1 = fmaxf(fmaf(x0, W1[2 * l + 1], x1 * W1[64 + 2 * l + 1]), 0.f);
            float s = fmaf(v0, v0, v1 * v1);
            #pragma unroll
            for (int m = 16; m; m >>= 1) s += __shfl_xor_sync(0xffffffffu, s, m);
            float inv = 1.f / fmaxf(sqrtf(s), 1e-12f);
            ((__half2*)(hh + (size_t)n * 64))[l] =
                __floats2half2_rn(v0 * inv, v1 * inv);
        }
    } else {
        int e = (b - (2 + INIT_BLKS)) * 256 + t;
        if (e < nE) {
            int r = er[e];
            int rprev = (e == 0) ? -1 : er[e - 1];
            for (int rr = rprev + 1; rr <= r; rr++) g_rowptr[rr] = e;
            if (e == nE - 1)
                for (int rr = r + 1; rr <= N_NODES; rr++) g_rowptr[rr] = nE;
        }
    }
}

// ---------------- SPMM v3: quarter-warp per edge, uint4 gathers -----------
__global__ void spmm(const __half* __restrict__ hh, const int* __restrict__ col,
                     const int* __restrict__ rp, __half* __restrict__ out) {
    int w = (blockIdx.x * blockDim.x + threadIdx.x) >> 5;
    if (w >= N_NODES) return;
    int lane = threadIdx.x & 31;
    int grp = lane >> 3;
    int q   = lane & 7;
    int s = rp[w], e = rp[w + 1];
    unsigned long long a0 = 0ull, a1 = 0ull, a2 = 0ull, a3 = 0ull;
    int i = s;
    for (; i + 16 <= e; i += 16) {
        int c[4];
        #pragma unroll
        for (int u = 0; u < 4; u++) c[u] = __ldg(col + i + 4 * u + grp);
        uint4 v[4];
        #pragma unroll
        for (int u = 0; u < 4; u++)
            v[u] = ((const uint4*)(hh + (size_t)c[u] * 64))[q];
        #pragma unroll
        for (int u = 0; u < 4; u++) {
            __half2* hp = (__half2*)&v[u];
            fadd2(a0, __half22float2(hp[0]));
            fadd2(a1, __half22float2(hp[1]));
            fadd2(a2, __half22float2(hp[2]));
            fadd2(a3, __half22float2(hp[3]));
        }
    }
    for (; i + 4 <= e; i += 4) {
        int c = __ldg(col + i + grp);
        uint4 v = ((const uint4*)(hh + (size_t)c * 64))[q];
        __half2* hp = (__half2*)&v;
        fadd2(a0, __half22float2(hp[0]));
        fadd2(a1, __half22float2(hp[1]));
        fadd2(a2, __half22float2(hp[2]));
        fadd2(a3, __half22float2(hp[3]));
    }
    if (grp < e - i) {
        int c = __ldg(col + i + grp);
        uint4 v = ((const uint4*)(hh + (size_t)c * 64))[q];
        __half2* hp = (__half2*)&v;
        fadd2(a0, __half22float2(hp[0]));
        fadd2(a1, __half22float2(hp[1]));
        fadd2(a2, __half22float2(hp[2]));
        fadd2(a3, __half22float2(hp[3]));
    }
    F2U A[4]; A[0].u = a0; A[1].u = a1; A[2].u = a2; A[3].u = a3;
    #pragma unroll
    for (int k = 0; k < 4; k++) {
        A[k].f.x += __shfl_xor_sync(0xffffffffu, A[k].f.x, 8);
        A[k].f.y += __shfl_xor_sync(0xffffffffu, A[k].f.y, 8);
        A[k].f.x += __shfl_xor_sync(0xffffffffu, A[k].f.x, 16);
        A[k].f.y += __shfl_xor_sync(0xffffffffu, A[k].f.y, 16);
    }
    if (grp == 0) {
        uint4 st;
        *(__half2*)&st.x = __floats2half2_rn(A[0].f.x, A[0].f.y);
        *(__half2*)&st.y = __floats2half2_rn(A[1].f.x, A[1].f.y);
        *(__half2*)&st.z = __floats2half2_rn(A[2].f.x, A[2].f.y);
        *(__half2*)&st.w = __floats2half2_rn(A[3].f.x, A[3].f.y);
        ((uint4*)(out + (size_t)w * 64))[q] = st;
    }
}

// ---------------- update_h: tensor-core HMMA (m16n8k16) -------------------
// mode 0: store fp16 h only; mode 1: store fp32 out only (final iter).
__global__ void __launch_bounds__(128, 6) update_h(
    const __half* __restrict__ hhin, const __half* __restrict__ hnv,
    const __half* __restrict__ Wt, const float* __restrict__ bl,
    float* __restrict__ out, __half* __restrict__ hho, int nrows, int mode) {
    __shared__ __half sA[64 * AST];   // A tile [node][k], 17408 B
    __shared__ __half sW[64 * AST];   // Wt     [n][k],    17408 B
    int t = threadIdx.x;
    int base = blockIdx.x * UH_NODES;
    for (int i = t; i < 1024; i += 128) {
        int r = i >> 4, c = i & 15;
        uint4 v = (c < 8)
            ? ((const uint4*)(hhin + (size_t)(base + r) * 64))[c]
            : ((const uint4*)(hnv + (size_t)(base + r) * 64))[c - 8];
        ((uint4*)sA)[r * 17 + c] = v;
        ((uint4*)sW)[r * 17 + c] = ((const uint4*)(Wt + r * 128))[c];
    }
    __syncthreads();

    int wid = t >> 5, lane = t & 31;
    int g = lane >> 2, tg = lane & 3;
    int m0 = wid * 16;

    float c0[8], c1[8], c2[8], c3[8];
    #pragma unroll
    for (int j = 0; j < 8; j++) {
        float b0 = bl[j * 8 + 2 * tg];
        float b1 = bl[j * 8 + 2 * tg + 1];
        c0[j] = b0; c1[j] = b1; c2[j] = b0; c3[j] = b1;
    }

    int mat = lane >> 3, mlow = lane & 7;
    #pragma unroll
    for (int ks = 0; ks < 8; ks++) {
        int k0 = ks * 16;
        uint32_t a0, a1, a2, a3;
        {
            int row = m0 + (mat & 1) * 8 + mlow;
            int colk = k0 + (mat >> 1) * 8;
            uint32_t addr = s2u(sA + row * AST + colk);
            asm volatile(
                "ldmatrix.sync.aligned.m8n8.x4.shared.b16 {%0,%1,%2,%3}, [%4];"
                : "=r"(a0), "=r"(a1), "=r"(a2), "=r"(a3) : "r"(addr));
        }
        #pragma unroll
        for (int jp = 0; jp < 4; jp++) {
            uint32_t b0, b1, b2, b3;
            int nrow = (jp * 2 + (mat >> 1)) * 8 + mlow;
            int kc = k0 + (mat & 1) * 8;
            uint32_t addr = s2u(sW + nrow * AST + kc);
            asm volatile(
                "ldmatrix.sync.aligned.m8n8.x4.shared.b16 {%0,%1,%2,%3}, [%4];"
                : "=r"(b0), "=r"(b1), "=r"(b2), "=r"(b3) : "r"(addr));
            int j = jp * 2;
            MMA16816(c0[j], c1[j], c2[j], c3[j], a0, a1, a2, a3, b0, b1);
            MMA16816(c0[j + 1], c1[j + 1], c2[j + 1], c3[j + 1],
                     a0, a1, a2, a3, b2, b3);
        }
    }

    float sa2 = 0.f, sb2 = 0.f;
    #pragma unroll
    for (int j = 0; j < 8; j++) {
        c0[j] = fmaxf(c0[j], 0.f); c1[j] = fmaxf(c1[j], 0.f);
        c2[j] = fmaxf(c2[j], 0.f); c3[j] = fmaxf(c3[j], 0.f);
        sa2 = fmaf(c0[j], c0[j], sa2); sa2 = fmaf(c1[j], c1[j], sa2);
        sb2 = fmaf(c2[j], c2[j], sb2); sb2 = fmaf(c3[j], c3[j], sb2);
    }
    sa2 += __shfl_xor_sync(0xffffffffu, sa2, 1);
    sa2 += __shfl_xor_sync(0xffffffffu, sa2, 2);
    sb2 += __shfl_xor_sync(0xffffffffu, sb2, 1);
    sb2 += __shfl_xor_sync(0xffffffffu, sb2, 2);
    float invA = 1.f / fmaxf(sqrtf(sa2), 1e-12f);
    float invB = 1.f / fmaxf(sqrtf(sb2), 1e-12f);

    int nA = base + m0 + g, nB = nA + 8;
    if (mode == 0) {
        if (nA < nrows) {
            #pragma unroll
            for (int j = 0; j < 8; j++)
                *(__half2*)(hho + (size_t)nA * 64 + j * 8 + 2 * tg) =
                    __floats2half2_rn(c0[j] * invA, c1[j] * invA);
        }
        if (nB < nrows) {
            #pragma unroll
            for (int j = 0; j < 8; j++)
                *(__half2*)(hho + (size_t)nB * 64 + j * 8 + 2 * tg) =
                    __floats2half2_rn(c2[j] * invB, c3[j] * invB);
        }
    } else {
        if (nA < nrows) {
            #pragma unroll
            for (int j = 0; j < 8; j++)
                *(float2*)(out + (size_t)nA * 64 + j * 8 + 2 * tg) =
                    make_float2(c0[j] * invA, c1[j] * invA);
        }
        if (nB < nrows) {
            #pragma unroll
            for (int j = 0; j < 8; j++)
                *(float2*)(out + (size_t)nB * 64 + j * 8 + 2 * tg) =
                    make_float2(c2[j] * invB, c3[j] * invB);
        }
    }
}

// ---------------- batchk: fused pool_partial + reduce + batch update ------
// blocks [0,PB): pool partials, then release via fence+atomicAdd(g_bflag).
// blocks [PB,PB+2): preload weights/hs, spin until g_bflag >= target,
// then fold 64 partials and run the batch GEMM epilogue. target = PB*(d+1)
// (flag accumulates across the 3 iterations; prep zeroes it per launch).
__global__ void __launch_bounds__(128) batchk(
    const __half* __restrict__ h, const int* __restrict__ ba,
    const float* __restrict__ bl, const float* __restrict__ hs,
    float* __restrict__ out, int n, int target) {
    __shared__ float sbuf[12288];   // 48 KB, dual-purpose
    int t = threadIdx.x;
    if (blockIdx.x < PB) {
        float* acc = sbuf;          // 2 x 4096
        for (int i = t; i < 8192; i += 128) acc[i] = 0.f;
        __syncthreads();
        int per = (n + PB - 1) / PB;
        int start = blockIdx.x * per;
        int end = min(start + per, n);
        int j = t & 63, nl = t >> 6;
        float* my = acc + nl * 4096;
        for (int nn = start + nl; nn < end; nn += 2) {
            int b = ba[nn];
            my[b * 64 + j] += __half2float(h[(size_t)nn * 64 + j]);
        }
        __syncthreads();
        for (int i = t; i < 4096; i += 128)
            g_pp[blockIdx.x * 4096 + i] = acc[i] + acc[4096 + i];
        __syncthreads();
        if (t == 0) { __threadfence(); atomicAdd(&g_bflag, 1); }
        return;
    }

    // ---- update_hs part ----
    float* sWa = sbuf;              // 4096
    float* sWb = sbuf + 4096;       // 4096
    float* sh  = sbuf + 8192;       // 2048
    float* shn = sbuf + 10240;      // 2048
    int base = (blockIdx.x - PB) * 32;
    for (int i = t; i < 1024; i += 128) {
        ((float4*)sWa)[i] = ((const float4*)g_Wa)[i];
        ((float4*)sWb)[i] = ((const float4*)g_Wb)[i];
    }
    for (int i = t; i < 512; i += 128)
        ((float4*)sh)[i] = ((const float4*)(hs + base * 64))[i];
    if (t == 0) {
        while (*(volatile int*)&g_bflag < target) __nanosleep(64);
        __threadfence();
    }
    __syncthreads();
    for (int i = t; i < 512; i += 128) {
        float4 s = make_float4(0.f, 0.f, 0.f, 0.f);
        #pragma unroll 8
        for (int b = 0; b < PB; b++) {
            float4 v = ((const float4*)g_pp)[b * 1024 + base * 16 + i];
            s.x += v.x; s.y += v.y; s.z += v.z; s.w += v.w;
        }
        ((float4*)shn)[i] = s;
    }
    __syncthreads();

    int nl = t >> 2, part = t & 3;
    float2 acc[8];
    #pragma unroll
    for (int i = 0; i < 8; i++) acc[i] = ((const float2*)bl)[part * 8 + i];

    const float4* wa4 = (const float4*)sWa;
    const float4* wb4 = (const float4*)sWb;
    const float* hr = sh + nl * 64;
    const float* hnr = shn + nl * 64;

    #pragma unroll 4
    for (int k = 0; k < 64; k++) {
        float a = hr[k], b = hnr[k];
        float2 a2 = make_float2(a, a), b2 = make_float2(b, b);
        #pragma unroll
        for (int i = 0; i < 4; i++) {
            float4 wa = wa4[k * 16 + part * 4 + i];
            ffma2(acc[2 * i],     a2, make_float2(wa.x, wa.y));
            ffma2(acc[2 * i + 1], a2, make_float2(wa.z, wa.w));
            float4 wb = wb4[k * 16 + part * 4 + i];
            ffma2(acc[2 * i],     b2, make_float2(wb.x, wb.y));
            ffma2(acc[2 * i + 1], b2, make_float2(wb.z, wb.w));
        }
    }

    float s = 0.f;
    #pragma unroll
    for (int i = 0; i < 8; i++) {
        acc[i].x = fmaxf(acc[i].x, 0.f);
        acc[i].y = fmaxf(acc[i].y, 0.f);
        s = fmaf(acc[i].x, acc[i].x, s);
        s = fmaf(acc[i].y, acc[i].y, s);
    }
    s += __shfl_xor_sync(0xffffffffu, s, 1);
    s += __shfl_xor_sync(0xffffffffu, s, 2);
    float inv = 1.f / fmaxf(sqrtf(s), 1e-12f);

    float4* o4 = (float4*)(out + (base + nl) * 64 + part * 16);
    #pragma unroll
    for (int i = 0; i < 4; i++)
        o4[i] = make_float4(acc[2 * i].x * inv, acc[2 * i].y * inv,
                            acc[2 * i + 1].x * inv, acc[2 * i + 1].y * inv);
}

// ---------------- host orchestration: 10 kernel nodes, 8 event nodes ------
extern "C" void kernel_launch(void* const* d_in, const int* in_sizes, int n_in,
                              void* d_out, int out_size) {
    const int*   edge_row     = (const int*)d_in[0];
    const int*   edge_col     = (const int*)d_in[1];
    const int*   batch_assign = (const int*)d_in[2];
    const float* X            = (const float*)d_in[3];
    const float* Xs           = (const float*)d_in[4];
    const float* W1           = (const float*)d_in[5];
    const float* W2           = (const float*)d_in[6];
    const float* W3           = (const float*)d_in[7];
    const float* Wl           = (const float*)d_in[8];
    const float* bl           = (const float*)d_in[9];
    float* out = (float*)d_out;

    int nE = in_sizes[0];

    float *hsA, *hsB;
    __half *hh0, *hh1, *hh2, *hnv, *Wt;
    int* rp;
    cudaGetSymbolAddress((void**)&hh0, g_hh0);
    cudaGetSymbolAddress((void**)&hh1, g_hh1);
    cudaGetSymbolAddress((void**)&hh2, g_hh2);
    cudaGetSymbolAddress((void**)&hnv, g_hnv);
    cudaGetSymbolAddress((void**)&hsA, g_hsA);
    cudaGetSymbolAddress((void**)&hsB, g_hsB);
    cudaGetSymbolAddress((void**)&Wt,  g_Wt);
    cudaGetSymbolAddress((void**)&rp,  g_rowptr);
    __half* hhbuf[3] = {hh0, hh1, hh2};

    cudaStream_t s1 = 0;   // capture (legacy) stream: node path
    cudaStream_t s2;       // batch path
    cudaStreamCreateWithFlags(&s2, cudaStreamNonBlocking);
    cudaEvent_t evFork, evEnd, evU[2];
    cudaEventCreateWithFlags(&evFork, cudaEventDisableTiming);
    cudaEventCreateWithFlags(&evEnd,  cudaEventDisableTiming);
    cudaEventCreateWithFlags(&evU[0], cudaEventDisableTiming);
    cudaEventCreateWithFlags(&evU[1], cudaEventDisableTiming);

    int prep_blocks = 2 + INIT_BLKS + (nE + 255) / 256;
    prep<<<prep_blocks, 256, 0, s1>>>(edge_row, nE, X, Xs, W1, W2, W3, Wl,
                                      hh0, hsA);
    cudaEventRecord(evFork, s1);
    cudaStreamWaitEvent(s2, evFork, 0);

    float* hsc = hsA; float* hsn = hsB;
    for (int d = 0; d < 3; d++) {
        __half* hhc = hhbuf[d % 3];
        __half* hhn = hhbuf[(d + 1) % 3];
        float*  hsout = (d == 2) ? (out + N_NODES * D_EMB) : hsn;
        int     mode  = (d == 2) ? 1 : 0;

        // node path (s1): idx prep[2], spmm0[3], uh0[4], batchk0[5] (ncu -s5)
        spmm<<<(N_NODES * 32 + 255) / 256, 256, 0, s1>>>(
            hhc, edge_col, rp, hnv);
        update_h<<<(NPAD / UH_NODES), 128, 0, s1>>>(
            hhc, hnv, Wt, bl, out, hhn, N_NODES, mode);
        if (d < 2) cudaEventRecord(evU[d], s1);

        // batch path (s2): fully fused single kernel
        if (d > 0) cudaStreamWaitEvent(s2, evU[d - 1], 0);
        batchk<<<PB + 2, 128, 0, s2>>>(hhc, batch_assign, bl, hsc, hsout,
                                       N_NODES, PB * (d + 1));

        float* tf = hsc; hsc = hsn; hsn = tf;
    }

    cudaEventRecord(evEnd, s2);
    cudaStreamWaitEvent(s1, evEnd, 0);   // join: all output visible on s1
}

// round 16
// speedup vs baseline: 1.7579x; 1.7579x over previous
#include <cuda_runtime.h>
#include <cuda_fp16.h>
#include <cstdint>

#define N_NODES 50000
#define NPAD    50048
#define D_EMB   64
#define N_BATCH 64
#define PB      128   // pool partial blocks
#define UH_NODES 64   // nodes per update_h block
#define AST     136   // smem row stride in halves (272B = 17 uint4)

// ---------------- scratch (device globals; no allocation) ----------------
__device__ __half g_hh0[NPAD * D_EMB];          // fp16 h, triple-buffered
__device__ __half g_hh1[NPAD * D_EMB];
__device__ __half g_hh2[NPAD * D_EMB];
__device__ __half g_hnv[NPAD * D_EMB];          // fp16 spmm output
__device__ float  g_hsA[N_BATCH * D_EMB];
__device__ float  g_hsB[N_BATCH * D_EMB];
__device__ float  g_Wa[D_EMB * D_EMB];
__device__ float  g_Wb[D_EMB * D_EMB];
__device__ __half g_Wt[D_EMB * 2 * D_EMB];      // fused weights, [n=64][k=128] fp16
__device__ int    g_rowptr[N_NODES + 1];
__device__ float  g_pp[PB * N_BATCH * D_EMB];
__device__ float  g_ppq[4 * N_BATCH * D_EMB];

// ---------------- packed f32x2 helpers ------------------------------------
union F2U { float2 f; unsigned long long u; };
__device__ __forceinline__ void ffma2(float2& c, float2 a, float2 b) {
    F2U A, B, C; A.f = a; B.f = b; C.f = c;
    asm("fma.rn.f32x2 %0, %1, %2, %0;" : "+l"(C.u) : "l"(A.u), "l"(B.u));
    c = C.f;
}
__device__ __forceinline__ void fadd2(unsigned long long& acc, float2 v) {
    F2U V; V.f = v;
    asm("add.rn.f32x2 %0, %0, %1;" : "+l"(acc) : "l"(V.u));
}

__device__ __forceinline__ uint32_t s2u(const void* p) {
    return (uint32_t)__cvta_generic_to_shared(p);
}

#define MMA16816(c0, c1, c2, c3, a0, a1, a2, a3, b0, b1)                       \
    asm volatile(                                                              \
        "mma.sync.aligned.m16n8k16.row.col.f32.f16.f16.f32 "                   \
        "{%0,%1,%2,%3}, {%4,%5,%6,%7}, {%8,%9}, {%0,%1,%2,%3};"                \
        : "+f"(c0), "+f"(c1), "+f"(c2), "+f"(c3)                               \
        : "r"(a0), "r"(a1), "r"(a2), "r"(a3), "r"(b0), "r"(b1))

// ---------------- prep: fuse_w + init_h + init_hs + rowptr, one launch ----
#define INIT_BLKS ((N_NODES + 7) / 8)   // warp per node, 8 warps/block

__global__ void prep(const int* __restrict__ er, int nE,
                     const float* __restrict__ X, const float* __restrict__ Xs,
                     const float* __restrict__ W1, const float* __restrict__ W2,
                     const float* __restrict__ W3, const float* __restrict__ Wl,
                     __half* __restrict__ hh, float* __restrict__ hs) {
    __shared__ float sWl[8192];   // full Wl [128,64], 32 KB (block 0 only)
    int b = blockIdx.x, t = threadIdx.x;
    if (b == 0) {
        for (int i = t; i < 2048; i += 256)
            ((float4*)sWl)[i] = ((const float4*)Wl)[i];
        __syncthreads();
        for (int o = t; o < 4096; o += 256) {
            int i = o >> 6, j = o & 63;   // i = input dim (k), j = output dim (n)
            float sa = 0.f, sb = 0.f;
            #pragma unroll 8
            for (int k = 0; k < 64; k++) {
                sa = fmaf(W2[i * 64 + k], sWl[k * 64 + j], sa);
                sb = fmaf(W3[i * 64 + k], sWl[(64 + k) * 64 + j], sb);
            }
            g_Wa[o] = sa; g_Wb[o] = sb;
            g_Wt[j * 128 + i]      = __float2half(sa);   // Wt[n][k]      (h part)
            g_Wt[j * 128 + 64 + i] = __float2half(sb);   // Wt[n][64+k]   (hnv part)
        }
    } else if (b == 1) {
        if (t < N_BATCH) {
            float x0 = Xs[t * 2], x1 = Xs[t * 2 + 1];
            float s = 0.f;
            #pragma unroll
            for (int j = 0; j < 64; j++) {
                float v = fmaxf(fmaf(x0, W1[j], x1 * W1[64 + j]), 0.f);
                s = fmaf(v, v, s);
            }
            float inv = 1.f / fmaxf(sqrtf(s), 1e-12f);
            #pragma unroll
            for (int j = 0; j < 64; j++) {
                float v = fmaxf(fmaf(x0, W1[j], x1 * W1[64 + j]), 0.f);
                hs[t * 64 + j] = v * inv;
            }
        }
    } else if (b < 2 + INIT_BLKS) {
        // warp per node, lanes own dims (2l, 2l+1); coalesced half2 stores
        int wid = t >> 5, l = t & 31;
        int n = (b - 2) * 8 + wid;
        if (n < N_NODES) {
            float x0 = X[n * 2], x1 = X[n * 2 + 1];
            float v0 = fmaxf(fmaf(x0, W1[2 * l],     x1 * W1[64 + 2 * l]),     0.f);
            float v1 = fmaxf(fmaf(x0, W1[2 * l + 1], x1 * W1[64 + 2 * l + 1]), 0.f);
            float s = fmaf(v0, v0, v1 * v1);
            #pragma unroll
            for (int m = 16; m; m >>= 1) s += __shfl_xor_sync(0xffffffffu, s, m);
            float inv = 1.f / fmaxf(sqrtf(s), 1e-12f);
            ((__half2*)(hh + (size_t)n * 64))[l] =
                __floats2half2_rn(v0 * inv, v1 * inv);
        }
    } else {
        int e = (b - (2 + INIT_BLKS)) * 256 + t;
        if (e < nE) {
            int r = er[e];
            int rprev = (e == 0) ? -1 : er[e - 1];
            for (int rr = rprev + 1; rr <= r; rr++) g_rowptr[rr] = e;
            if (e == nE - 1)
                for (int rr = r + 1; rr <= N_NODES; rr++) g_rowptr[rr] = nE;
        }
    }
}

// ---------------- SPMM v3: quarter-warp per edge, uint4 gathers -----------
__global__ void spmm(const __half* __restrict__ hh, const int* __restrict__ col,
                     const int* __restrict__ rp, __half* __restrict__ out) {
    int w = (blockIdx.x * blockDim.x + threadIdx.x) >> 5;
    if (w >= N_NODES) return;
    int lane = threadIdx.x & 31;
    int grp = lane >> 3;
    int q   = lane & 7;
    int s = rp[w], e = rp[w + 1];
    unsigned long long a0 = 0ull, a1 = 0ull, a2 = 0ull, a3 = 0ull;
    int i = s;
    for (; i + 16 <= e; i += 16) {
        int c[4];
        #pragma unroll
        for (int u = 0; u < 4; u++) c[u] = __ldg(col + i + 4 * u + grp);
        uint4 v[4];
        #pragma unroll
        for (int u = 0; u < 4; u++)
            v[u] = ((const uint4*)(hh + (size_t)c[u] * 64))[q];
        #pragma unroll
        for (int u = 0; u < 4; u++) {
            __half2* hp = (__half2*)&v[u];
            fadd2(a0, __half22float2(hp[0]));
            fadd2(a1, __half22float2(hp[1]));
            fadd2(a2, __half22float2(hp[2]));
            fadd2(a3, __half22float2(hp[3]));
        }
    }
    for (; i + 4 <= e; i += 4) {
        int c = __ldg(col + i + grp);
        uint4 v = ((const uint4*)(hh + (size_t)c * 64))[q];
        __half2* hp = (__half2*)&v;
        fadd2(a0, __half22float2(hp[0]));
        fadd2(a1, __half22float2(hp[1]));
        fadd2(a2, __half22float2(hp[2]));
        fadd2(a3, __half22float2(hp[3]));
    }
    if (grp < e - i) {
        int c = __ldg(col + i + grp);
        uint4 v = ((const uint4*)(hh + (size_t)c * 64))[q];
        __half2* hp = (__half2*)&v;
        fadd2(a0, __half22float2(hp[0]));
        fadd2(a1, __half22float2(hp[1]));
        fadd2(a2, __half22float2(hp[2]));
        fadd2(a3, __half22float2(hp[3]));
    }
    F2U A[4]; A[0].u = a0; A[1].u = a1; A[2].u = a2; A[3].u = a3;
    #pragma unroll
    for (int k = 0; k < 4; k++) {
        A[k].f.x += __shfl_xor_sync(0xffffffffu, A[k].f.x, 8);
        A[k].f.y += __shfl_xor_sync(0xffffffffu, A[k].f.y, 8);
        A[k].f.x += __shfl_xor_sync(0xffffffffu, A[k].f.x, 16);
        A[k].f.y += __shfl_xor_sync(0xffffffffu, A[k].f.y, 16);
    }
    if (grp == 0) {
        uint4 st;
        *(__half2*)&st.x = __floats2half2_rn(A[0].f.x, A[0].f.y);
        *(__half2*)&st.y = __floats2half2_rn(A[1].f.x, A[1].f.y);
        *(__half2*)&st.z = __floats2half2_rn(A[2].f.x, A[2].f.y);
        *(__half2*)&st.w = __floats2half2_rn(A[3].f.x, A[3].f.y);
        ((uint4*)(out + (size_t)w * 64))[q] = st;
    }
}

// ---------------- batch pooling stage 1 (fp16, 4-deep MLP) ----------------
__global__ void __launch_bounds__(128) pool_partial(const __half* __restrict__ h,
                                                    const int* __restrict__ ba, int n) {
    __shared__ float acc[2 * N_BATCH * D_EMB];  // 32 KB
    int t = threadIdx.x;
    for (int i = t; i < 2 * 4096; i += 128) acc[i] = 0.f;
    __syncthreads();
    int per = (n + PB - 1) / PB;
    int start = blockIdx.x * per;
    int end = min(start + per, n);
    int j = t & 63;
    int nl = t >> 6;
    float* my = acc + nl * 4096;
    int nn = start + nl;
    // 4-deep: independent index + value loads before the smem adds
    for (; nn + 6 < end; nn += 8) {
        int b0 = __ldg(ba + nn);
        int b1 = __ldg(ba + nn + 2);
        int b2 = __ldg(ba + nn + 4);
        int b3 = __ldg(ba + nn + 6);
        float v0 = __half2float(h[(size_t)nn * 64 + j]);
        float v1 = __half2float(h[(size_t)(nn + 2) * 64 + j]);
        float v2 = __half2float(h[(size_t)(nn + 4) * 64 + j]);
        float v3 = __half2float(h[(size_t)(nn + 6) * 64 + j]);
        my[b0 * 64 + j] += v0;
        my[b1 * 64 + j] += v1;
        my[b2 * 64 + j] += v2;
        my[b3 * 64 + j] += v3;
    }
    for (; nn < end; nn += 2) {
        int b = __ldg(ba + nn);
        my[b * 64 + j] += __half2float(h[(size_t)nn * 64 + j]);
    }
    __syncthreads();
    for (int i = t; i < 4096; i += 128)
        g_pp[blockIdx.x * 4096 + i] = acc[i] + acc[4096 + i];
}

// ---------------- pooling stage 2: 4096 threads, float4, 4-way K-split ----
__global__ void pool_reduce() {
    int tid = blockIdx.x * blockDim.x + threadIdx.x;  // 4096
    int q = tid >> 10, i4 = tid & 1023;
    const float4* pp = (const float4*)g_pp;
    float4 s = make_float4(0.f, 0.f, 0.f, 0.f);
    #pragma unroll 8
    for (int b = q * 32; b < q * 32 + 32; b++) {
        float4 v = pp[b * 1024 + i4];
        s.x += v.x; s.y += v.y; s.z += v.z; s.w += v.w;
    }
    ((float4*)g_ppq)[q * 1024 + i4] = s;
}

// ---------------- update_h: tensor-core HMMA (m16n8k16) -------------------
// mode 0: store fp16 h only; mode 1: store fp32 out only (final iter).
__global__ void __launch_bounds__(128, 6) update_h(
    const __half* __restrict__ hhin, const __half* __restrict__ hnv,
    const __half* __restrict__ Wt, const float* __restrict__ bl,
    float* __restrict__ out, __half* __restrict__ hho, int nrows, int mode) {
    __shared__ __half sA[64 * AST];   // A tile [node][k], 17408 B
    __shared__ __half sW[64 * AST];   // Wt     [n][k],    17408 B
    int t = threadIdx.x;
    int base = blockIdx.x * UH_NODES;
    for (int i = t; i < 1024; i += 128) {
        int r = i >> 4, c = i & 15;
        uint4 v = (c < 8)
            ? ((const uint4*)(hhin + (size_t)(base + r) * 64))[c]
            : ((const uint4*)(hnv + (size_t)(base + r) * 64))[c - 8];
        ((uint4*)sA)[r * 17 + c] = v;
        ((uint4*)sW)[r * 17 + c] = ((const uint4*)(Wt + r * 128))[c];
    }
    __syncthreads();

    int wid = t >> 5, lane = t & 31;
    int g = lane >> 2, tg = lane & 3;
    int m0 = wid * 16;

    float c0[8], c1[8], c2[8], c3[8];
    #pragma unroll
    for (int j = 0; j < 8; j++) {
        float b0 = bl[j * 8 + 2 * tg];
        float b1 = bl[j * 8 + 2 * tg + 1];
        c0[j] = b0; c1[j] = b1; c2[j] = b0; c3[j] = b1;
    }

    int mat = lane >> 3, mlow = lane & 7;
    #pragma unroll
    for (int ks = 0; ks < 8; ks++) {
        int k0 = ks * 16;
        uint32_t a0, a1, a2, a3;
        {
            int row = m0 + (mat & 1) * 8 + mlow;
            int colk = k0 + (mat >> 1) * 8;
            uint32_t addr = s2u(sA + row * AST + colk);
            asm volatile(
                "ldmatrix.sync.aligned.m8n8.x4.shared.b16 {%0,%1,%2,%3}, [%4];"
                : "=r"(a0), "=r"(a1), "=r"(a2), "=r"(a3) : "r"(addr));
        }
        #pragma unroll
        for (int jp = 0; jp < 4; jp++) {
            uint32_t b0, b1, b2, b3;
            int nrow = (jp * 2 + (mat >> 1)) * 8 + mlow;
            int kc = k0 + (mat & 1) * 8;
            uint32_t addr = s2u(sW + nrow * AST + kc);
            asm volatile(
                "ldmatrix.sync.aligned.m8n8.x4.shared.b16 {%0,%1,%2,%3}, [%4];"
                : "=r"(b0), "=r"(b1), "=r"(b2), "=r"(b3) : "r"(addr));
            int j = jp * 2;
            MMA16816(c0[j], c1[j], c2[j], c3[j], a0, a1, a2, a3, b0, b1);
            MMA16816(c0[j + 1], c1[j + 1], c2[j + 1], c3[j + 1],
                     a0, a1, a2, a3, b2, b3);
        }
    }

    float sa2 = 0.f, sb2 = 0.f;
    #pragma unroll
    for (int j = 0; j < 8; j++) {
        c0[j] = fmaxf(c0[j], 0.f); c1[j] = fmaxf(c1[j], 0.f);
        c2[j] = fmaxf(c2[j], 0.f); c3[j] = fmaxf(c3[j], 0.f);
        sa2 = fmaf(c0[j], c0[j], sa2); sa2 = fmaf(c1[j], c1[j], sa2);
        sb2 = fmaf(c2[j], c2[j], sb2); sb2 = fmaf(c3[j], c3[j], sb2);
    }
    sa2 += __shfl_xor_sync(0xffffffffu, sa2, 1);
    sa2 += __shfl_xor_sync(0xffffffffu, sa2, 2);
    sb2 += __shfl_xor_sync(0xffffffffu, sb2, 1);
    sb2 += __shfl_xor_sync(0xffffffffu, sb2, 2);
    float invA = 1.f / fmaxf(sqrtf(sa2), 1e-12f);
    float invB = 1.f / fmaxf(sqrtf(sb2), 1e-12f);

    int nA = base + m0 + g, nB = nA + 8;
    if (mode == 0) {
        if (nA < nrows) {
            #pragma unroll
            for (int j = 0; j < 8; j++)
                *(__half2*)(hho + (size_t)nA * 64 + j * 8 + 2 * tg) =
                    __floats2half2_rn(c0[j] * invA, c1[j] * invA);
        }
        if (nB < nrows) {
            #pragma unroll
            for (int j = 0; j < 8; j++)
                *(__half2*)(hho + (size_t)nB * 64 + j * 8 + 2 * tg) =
                    __floats2half2_rn(c2[j] * invB, c3[j] * invB);
        }
    } else {
        if (nA < nrows) {
            #pragma unroll
            for (int j = 0; j < 8; j++)
                *(float2*)(out + (size_t)nA * 64 + j * 8 + 2 * tg) =
                    make_float2(c0[j] * invA, c1[j] * invA);
        }
        if (nB < nrows) {
            #pragma unroll
            for (int j = 0; j < 8; j++)
                *(float2*)(out + (size_t)nB * 64 + j * 8 + 2 * tg) =
                    make_float2(c2[j] * invB, c3[j] * invB);
        }
    }
}

// ---------------- batch update (folds 4-quarter reduce) -------------------
__global__ void __launch_bounds__(128) update_hs(
    const float* __restrict__ hs, const float* __restrict__ bl,
    float* __restrict__ out) {
    __shared__ float sWa[4096], sWb[4096];
    __shared__ float sh[2048], shn[2048];
    int t = threadIdx.x;
    int base = blockIdx.x * 32;
    for (int i = t; i < 1024; i += 128) {
        ((float4*)sWa)[i] = ((const float4*)g_Wa)[i];
        ((float4*)sWb)[i] = ((const float4*)g_Wb)[i];
    }
    for (int i = t; i < 512; i += 128)
        ((float4*)sh)[i] = ((const float4*)(hs + base * 64))[i];
    for (int i = t; i < 512; i += 128) {
        float4 s = make_float4(0.f, 0.f, 0.f, 0.f);
        #pragma unroll
        for (int q = 0; q < 4; q++) {
            float4 v = ((const float4*)g_ppq)[q * 1024 + base * 16 + i];
            s.x += v.x; s.y += v.y; s.z += v.z; s.w += v.w;
        }
        ((float4*)shn)[i] = s;
    }
    __syncthreads();

    int nl = t >> 2, part = t & 3;
    float2 acc[8];
    #pragma unroll
    for (int i = 0; i < 8; i++) acc[i] = ((const float2*)bl)[part * 8 + i];

    const float4* wa4 = (const float4*)sWa;
    const float4* wb4 = (const float4*)sWb;
    const float* hr = sh + nl * 64;
    const float* hnr = shn + nl * 64;

    #pragma unroll 4
    for (int k = 0; k < 64; k++) {
        float a = hr[k], b = hnr[k];
        float2 a2 = make_float2(a, a), b2 = make_float2(b, b);
        #pragma unroll
        for (int i = 0; i < 4; i++) {
            float4 wa = wa4[k * 16 + part * 4 + i];
            ffma2(acc[2 * i],     a2, make_float2(wa.x, wa.y));
            ffma2(acc[2 * i + 1], a2, make_float2(wa.z, wa.w));
            float4 wb = wb4[k * 16 + part * 4 + i];
            ffma2(acc[2 * i],     b2, make_float2(wb.x, wb.y));
            ffma2(acc[2 * i + 1], b2, make_float2(wb.z, wb.w));
        }
    }

    float s = 0.f;
    #pragma unroll
    for (int i = 0; i < 8; i++) {
        acc[i].x = fmaxf(acc[i].x, 0.f);
        acc[i].y = fmaxf(acc[i].y, 0.f);
        s = fmaf(acc[i].x, acc[i].x, s);
        s = fmaf(acc[i].y, acc[i].y, s);
    }
    s += __shfl_xor_sync(0xffffffffu, s, 1);
    s += __shfl_xor_sync(0xffffffffu, s, 2);
    float inv = 1.f / fmaxf(sqrtf(s), 1e-12f);

    float4* o4 = (float4*)(out + (base + nl) * 64 + part * 16);
    #pragma unroll
    for (int i = 0; i < 4; i++)
        o4[i] = make_float4(acc[2 * i].x * inv, acc[2 * i].y * inv,
                            acc[2 * i + 1].x * inv, acc[2 * i + 1].y * inv);
}

// ---------------- host orchestration: dual-stream, triple-buffered hh -----
extern "C" void kernel_launch(void* const* d_in, const int* in_sizes, int n_in,
                              void* d_out, int out_size) {
    const int*   edge_row     = (const int*)d_in[0];
    const int*   edge_col     = (const int*)d_in[1];
    const int*   batch_assign = (const int*)d_in[2];
    const float* X            = (const float*)d_in[3];
    const float* Xs           = (const float*)d_in[4];
    const float* W1           = (const float*)d_in[5];
    const float* W2           = (const float*)d_in[6];
    const float* W3           = (const float*)d_in[7];
    const float* Wl           = (const float*)d_in[8];
    const float* bl           = (const float*)d_in[9];
    float* out = (float*)d_out;

    int nE = in_sizes[0];

    float *hsA, *hsB;
    __half *hh0, *hh1, *hh2, *hnv, *Wt;
    int* rp;
    cudaGetSymbolAddress((void**)&hh0, g_hh0);
    cudaGetSymbolAddress((void**)&hh1, g_hh1);
    cudaGetSymbolAddress((void**)&hh2, g_hh2);
    cudaGetSymbolAddress((void**)&hnv, g_hnv);
    cudaGetSymbolAddress((void**)&hsA, g_hsA);
    cudaGetSymbolAddress((void**)&hsB, g_hsB);
    cudaGetSymbolAddress((void**)&Wt,  g_Wt);
    cudaGetSymbolAddress((void**)&rp,  g_rowptr);
    __half* hhbuf[3] = {hh0, hh1, hh2};

    cudaStream_t s1 = 0;   // capture (legacy) stream: node path
    cudaStream_t s2;       // batch path
    cudaStreamCreateWithFlags(&s2, cudaStreamNonBlocking);
    cudaEvent_t evFork, evEnd, evU[2], evP0;
    cudaEventCreateWithFlags(&evFork, cudaEventDisableTiming);
    cudaEventCreateWithFlags(&evEnd,  cudaEventDisableTiming);
    cudaEventCreateWithFlags(&evU[0], cudaEventDisableTiming);
    cudaEventCreateWithFlags(&evU[1], cudaEventDisableTiming);
    cudaEventCreateWithFlags(&evP0,   cudaEventDisableTiming);

    int prep_blocks = 2 + INIT_BLKS + (nE + 255) / 256;
    prep<<<prep_blocks, 256, 0, s1>>>(edge_row, nE, X, Xs, W1, W2, W3, Wl,
                                      hh0, hsA);
    cudaEventRecord(evFork, s1);
    cudaStreamWaitEvent(s2, evFork, 0);

    float* hsc = hsA; float* hsn = hsB;
    for (int d = 0; d < 3; d++) {
        __half* hhc = hhbuf[d % 3];
        __half* hhn = hhbuf[(d + 1) % 3];
        float*  hsout = (d == 2) ? (out + N_NODES * D_EMB) : hsn;
        int     mode  = (d == 2) ? 1 : 0;

        if (d == 0) {
            // host idx: prep[2], spmm[3], update_h[4], pool_partial[5] -> ncu -s5
            spmm<<<(N_NODES * 32 + 255) / 256, 256, 0, s1>>>(
                hhc, edge_col, rp, hnv);
            update_h<<<(NPAD / UH_NODES), 128, 0, s1>>>(
                hhc, hnv, Wt, bl, out, hhn, N_NODES, mode);
            cudaEventRecord(evU[d], s1);
            pool_partial<<<PB, 128, 0, s2>>>(hhc, batch_assign, N_NODES);
            cudaEventRecord(evP0, s2);
            pool_reduce<<<16, 256, 0, s2>>>();
            update_hs<<<2, 128, 0, s2>>>(hsc, bl, hsout);
        } else {
            cudaStreamWaitEvent(s2, evU[d - 1], 0);   // pool reads h(d)
            spmm<<<(N_NODES * 32 + 255) / 256, 256, 0, s1>>>(
                hhc, edge_col, rp, hnv);
            pool_partial<<<PB, 128, 0, s2>>>(hhc, batch_assign, N_NODES);
            pool_reduce<<<16, 256, 0, s2>>>();
            update_hs<<<2, 128, 0, s2>>>(hsc, bl, hsout);

            // WAR: update_h(2) writes hh0, which pool_partial(0) read
            if (d == 2) cudaStreamWaitEvent(s1, evP0, 0);
            update_h<<<(NPAD / UH_NODES), 128, 0, s1>>>(
                hhc, hnv, Wt, bl, out, hhn, N_NODES, mode);
            if (d < 2) cudaEventRecord(evU[d], s1);
        }

        float* tf = hsc; hsc = hsn; hsn = tf;
    }

    cudaEventRecord(evEnd, s2);
    cudaStreamWaitEvent(s1, evEnd, 0);   // join: all output visible on s1
}

// round 17
// speedup vs baseline: 1.9374x; 1.1021x over previous
#include <cuda_runtime.h>
#include <cuda_fp16.h>
#include <cstdint>

#define N_NODES 50000
#define NPAD    50048
#define D_EMB   64
#define N_BATCH 64
#define PB      512   // pool partial blocks
#define NQ      16    // pool_reduce K-split
#define UH_NODES 64   // nodes per update_h block
#define AST     136   // smem row stride in halves (272B = 17 uint4)

// ---------------- scratch (device globals; no allocation) ----------------
__device__ __half g_hh0[NPAD * D_EMB];          // fp16 h, triple-buffered
__device__ __half g_hh1[NPAD * D_EMB];
__device__ __half g_hh2[NPAD * D_EMB];
__device__ __half g_hnv[NPAD * D_EMB];          // fp16 spmm output
__device__ float  g_hsA[N_BATCH * D_EMB];
__device__ float  g_hsB[N_BATCH * D_EMB];
__device__ float  g_Wa[D_EMB * D_EMB];
__device__ float  g_Wb[D_EMB * D_EMB];
__device__ __half g_Wt[D_EMB * 2 * D_EMB];      // fused weights, [n=64][k=128] fp16
__device__ int    g_rowptr[N_NODES + 1];
__device__ float  g_pp[PB * N_BATCH * D_EMB];   // 8 MB partials
__device__ float  g_ppq[NQ * N_BATCH * D_EMB];

// ---------------- packed f32x2 helpers ------------------------------------
union F2U { float2 f; unsigned long long u; };
__device__ __forceinline__ void ffma2(float2& c, float2 a, float2 b) {
    F2U A, B, C; A.f = a; B.f = b; C.f = c;
    asm("fma.rn.f32x2 %0, %1, %2, %0;" : "+l"(C.u) : "l"(A.u), "l"(B.u));
    c = C.f;
}
__device__ __forceinline__ void fadd2(unsigned long long& acc, float2 v) {
    F2U V; V.f = v;
    asm("add.rn.f32x2 %0, %0, %1;" : "+l"(acc) : "l"(V.u));
}

__device__ __forceinline__ uint32_t s2u(const void* p) {
    return (uint32_t)__cvta_generic_to_shared(p);
}

#define MMA16816(c0, c1, c2, c3, a0, a1, a2, a3, b0, b1)                       \
    asm volatile(                                                              \
        "mma.sync.aligned.m16n8k16.row.col.f32.f16.f16.f32 "                   \
        "{%0,%1,%2,%3}, {%4,%5,%6,%7}, {%8,%9}, {%0,%1,%2,%3};"                \
        : "+f"(c0), "+f"(c1), "+f"(c2), "+f"(c3)                               \
        : "r"(a0), "r"(a1), "r"(a2), "r"(a3), "r"(b0), "r"(b1))

// ---------------- prep: fuse_w + init_h + init_hs + rowptr, one launch ----
#define INIT_BLKS ((N_NODES + 7) / 8)   // warp per node, 8 warps/block

__global__ void prep(const int* __restrict__ er, int nE,
                     const float* __restrict__ X, const float* __restrict__ Xs,
                     const float* __restrict__ W1, const float* __restrict__ W2,
                     const float* __restrict__ W3, const float* __restrict__ Wl,
                     __half* __restrict__ hh, float* __restrict__ hs) {
    __shared__ float sWl[8192];   // full Wl [128,64], 32 KB (block 0 only)
    int b = blockIdx.x, t = threadIdx.x;
    if (b == 0) {
        for (int i = t; i < 2048; i += 256)
            ((float4*)sWl)[i] = ((const float4*)Wl)[i];
        __syncthreads();
        for (int o = t; o < 4096; o += 256) {
            int i = o >> 6, j = o & 63;   // i = input dim (k), j = output dim (n)
            float sa = 0.f, sb = 0.f;
            #pragma unroll 8
            for (int k = 0; k < 64; k++) {
                sa = fmaf(W2[i * 64 + k], sWl[k * 64 + j], sa);
                sb = fmaf(W3[i * 64 + k], sWl[(64 + k) * 64 + j], sb);
            }
            g_Wa[o] = sa; g_Wb[o] = sb;
            g_Wt[j * 128 + i]      = __float2half(sa);   // Wt[n][k]      (h part)
            g_Wt[j * 128 + 64 + i] = __float2half(sb);   // Wt[n][64+k]   (hnv part)
        }
    } else if (b == 1) {
        if (t < N_BATCH) {
            float x0 = Xs[t * 2], x1 = Xs[t * 2 + 1];
            float s = 0.f;
            #pragma unroll
            for (int j = 0; j < 64; j++) {
                float v = fmaxf(fmaf(x0, W1[j], x1 * W1[64 + j]), 0.f);
                s = fmaf(v, v, s);
            }
            float inv = 1.f / fmaxf(sqrtf(s), 1e-12f);
            #pragma unroll
            for (int j = 0; j < 64; j++) {
                float v = fmaxf(fmaf(x0, W1[j], x1 * W1[64 + j]), 0.f);
                hs[t * 64 + j] = v * inv;
            }
        }
    } else if (b < 2 + INIT_BLKS) {
        // warp per node, lanes own dims (2l, 2l+1); coalesced half2 stores
        int wid = t >> 5, l = t & 31;
        int n = (b - 2) * 8 + wid;
        if (n < N_NODES) {
            float x0 = X[n * 2], x1 = X[n * 2 + 1];
            float v0 = fmaxf(fmaf(x0, W1[2 * l],     x1 * W1[64 + 2 * l]),     0.f);
            float v1 = fmaxf(fmaf(x0, W1[2 * l + 1], x1 * W1[64 + 2 * l + 1]), 0.f);
            float s = fmaf(v0, v0, v1 * v1);
            #pragma unroll
            for (int m = 16; m; m >>= 1) s += __shfl_xor_sync(0xffffffffu, s, m);
            float inv = 1.f / fmaxf(sqrtf(s), 1e-12f);
            ((__half2*)(hh + (size_t)n * 64))[l] =
                __floats2half2_rn(v0 * inv, v1 * inv);
        }
    } else {
        int e = (b - (2 + INIT_BLKS)) * 256 + t;
        if (e < nE) {
            int r = er[e];
            int rprev = (e == 0) ? -1 : er[e - 1];
            for (int rr = rprev + 1; rr <= r; rr++) g_rowptr[rr] = e;
            if (e == nE - 1)
                for (int rr = r + 1; rr <= N_NODES; rr++) g_rowptr[rr] = nE;
        }
    }
}

// ---------------- SPMM v3: quarter-warp per edge, uint4 gathers -----------
__global__ void spmm(const __half* __restrict__ hh, const int* __restrict__ col,
                     const int* __restrict__ rp, __half* __restrict__ out) {
    int w = (blockIdx.x * blockDim.x + threadIdx.x) >> 5;
    if (w >= N_NODES) return;
    int lane = threadIdx.x & 31;
    int grp = lane >> 3;
    int q   = lane & 7;
    int s = rp[w], e = rp[w + 1];
    unsigned long long a0 = 0ull, a1 = 0ull, a2 = 0ull, a3 = 0ull;
    int i = s;
    for (; i + 16 <= e; i += 16) {
        int c[4];
        #pragma unroll
        for (int u = 0; u < 4; u++) c[u] = __ldg(col + i + 4 * u + grp);
        uint4 v[4];
        #pragma unroll
        for (int u = 0; u < 4; u++)
            v[u] = ((const uint4*)(hh + (size_t)c[u] * 64))[q];
        #pragma unroll
        for (int u = 0; u < 4; u++) {
            __half2* hp = (__half2*)&v[u];
            fadd2(a0, __half22float2(hp[0]));
            fadd2(a1, __half22float2(hp[1]));
            fadd2(a2, __half22float2(hp[2]));
            fadd2(a3, __half22float2(hp[3]));
        }
    }
    for (; i + 4 <= e; i += 4) {
        int c = __ldg(col + i + grp);
        uint4 v = ((const uint4*)(hh + (size_t)c * 64))[q];
        __half2* hp = (__half2*)&v;
        fadd2(a0, __half22float2(hp[0]));
        fadd2(a1, __half22float2(hp[1]));
        fadd2(a2, __half22float2(hp[2]));
        fadd2(a3, __half22float2(hp[3]));
    }
    if (grp < e - i) {
        int c = __ldg(col + i + grp);
        uint4 v = ((const uint4*)(hh + (size_t)c * 64))[q];
        __half2* hp = (__half2*)&v;
        fadd2(a0, __half22float2(hp[0]));
        fadd2(a1, __half22float2(hp[1]));
        fadd2(a2, __half22float2(hp[2]));
        fadd2(a3, __half22float2(hp[3]));
    }
    F2U A[4]; A[0].u = a0; A[1].u = a1; A[2].u = a2; A[3].u = a3;
    #pragma unroll
    for (int k = 0; k < 4; k++) {
        A[k].f.x += __shfl_xor_sync(0xffffffffu, A[k].f.x, 8);
        A[k].f.y += __shfl_xor_sync(0xffffffffu, A[k].f.y, 8);
        A[k].f.x += __shfl_xor_sync(0xffffffffu, A[k].f.x, 16);
        A[k].f.y += __shfl_xor_sync(0xffffffffu, A[k].f.y, 16);
    }
    if (grp == 0) {
        uint4 st;
        *(__half2*)&st.x = __floats2half2_rn(A[0].f.x, A[0].f.y);
        *(__half2*)&st.y = __floats2half2_rn(A[1].f.x, A[1].f.y);
        *(__half2*)&st.z = __floats2half2_rn(A[2].f.x, A[2].f.y);
        *(__half2*)&st.w = __floats2half2_rn(A[3].f.x, A[3].f.y);
        ((uint4*)(out + (size_t)w * 64))[q] = st;
    }
}

// ---------------- batch pooling stage 1: 512 blocks, ~49 nodes each -------
__global__ void __launch_bounds__(128) pool_partial(const __half* __restrict__ h,
                                                    const int* __restrict__ ba, int n) {
    __shared__ float acc[2 * N_BATCH * D_EMB];  // 32 KB
    int t = threadIdx.x;
    for (int i = t; i < 2 * 4096; i += 128) acc[i] = 0.f;
    __syncthreads();
    int per = (n + PB - 1) / PB;
    int start = blockIdx.x * per;
    int end = min(start + per, n);
    int j = t & 63;
    int nl = t >> 6;
    float* my = acc + nl * 4096;
    int nn = start + nl;
    for (; nn + 6 < end; nn += 8) {
        int b0 = __ldg(ba + nn);
        int b1 = __ldg(ba + nn + 2);
        int b2 = __ldg(ba + nn + 4);
        int b3 = __ldg(ba + nn + 6);
        float v0 = __half2float(h[(size_t)nn * 64 + j]);
        float v1 = __half2float(h[(size_t)(nn + 2) * 64 + j]);
        float v2 = __half2float(h[(size_t)(nn + 4) * 64 + j]);
        float v3 = __half2float(h[(size_t)(nn + 6) * 64 + j]);
        my[b0 * 64 + j] += v0;
        my[b1 * 64 + j] += v1;
        my[b2 * 64 + j] += v2;
        my[b3 * 64 + j] += v3;
    }
    for (; nn < end; nn += 2) {
        int b = __ldg(ba + nn);
        my[b * 64 + j] += __half2float(h[(size_t)nn * 64 + j]);
    }
    __syncthreads();
    for (int i = t; i < 4096; i += 128)
        g_pp[(size_t)blockIdx.x * 4096 + i] = acc[i] + acc[4096 + i];
}

// ---------------- pooling stage 2: 16-way K-split, 16384 threads ----------
__global__ void pool_reduce() {
    int tid = blockIdx.x * blockDim.x + threadIdx.x;  // 64 x 256 = 16384
    int q = tid >> 10, i4 = tid & 1023;
    const float4* pp = (const float4*)g_pp;
    float4 s = make_float4(0.f, 0.f, 0.f, 0.f);
    #pragma unroll 8
    for (int b = q * 32; b < q * 32 + 32; b++) {
        float4 v = pp[(size_t)b * 1024 + i4];
        s.x += v.x; s.y += v.y; s.z += v.z; s.w += v.w;
    }
    ((float4*)g_ppq)[q * 1024 + i4] = s;
}

// ---------------- update_h: tensor-core HMMA (m16n8k16) -------------------
// mode 0: store fp16 h only; mode 1: store fp32 out only (final iter).
__global__ void __launch_bounds__(128, 6) update_h(
    const __half* __restrict__ hhin, const __half* __restrict__ hnv,
    const __half* __restrict__ Wt, const float* __restrict__ bl,
    float* __restrict__ out, __half* __restrict__ hho, int nrows, int mode) {
    __shared__ __half sA[64 * AST];   // A tile [node][k], 17408 B
    __shared__ __half sW[64 * AST];   // Wt     [n][k],    17408 B
    int t = threadIdx.x;
    int base = blockIdx.x * UH_NODES;
    for (int i = t; i < 1024; i += 128) {
        int r = i >> 4, c = i & 15;
        uint4 v = (c < 8)
            ? ((const uint4*)(hhin + (size_t)(base + r) * 64))[c]
            : ((const uint4*)(hnv + (size_t)(base + r) * 64))[c - 8];
        ((uint4*)sA)[r * 17 + c] = v;
        ((uint4*)sW)[r * 17 + c] = ((const uint4*)(Wt + r * 128))[c];
    }
    __syncthreads();

    int wid = t >> 5, lane = t & 31;
    int g = lane >> 2, tg = lane & 3;
    int m0 = wid * 16;

    float c0[8], c1[8], c2[8], c3[8];
    #pragma unroll
    for (int j = 0; j < 8; j++) {
        float b0 = bl[j * 8 + 2 * tg];
        float b1 = bl[j * 8 + 2 * tg + 1];
        c0[j] = b0; c1[j] = b1; c2[j] = b0; c3[j] = b1;
    }

    int mat = lane >> 3, mlow = lane & 7;
    #pragma unroll
    for (int ks = 0; ks < 8; ks++) {
        int k0 = ks * 16;
        uint32_t a0, a1, a2, a3;
        {
            int row = m0 + (mat & 1) * 8 + mlow;
            int colk = k0 + (mat >> 1) * 8;
            uint32_t addr = s2u(sA + row * AST + colk);
            asm volatile(
                "ldmatrix.sync.aligned.m8n8.x4.shared.b16 {%0,%1,%2,%3}, [%4];"
                : "=r"(a0), "=r"(a1), "=r"(a2), "=r"(a3) : "r"(addr));
        }
        #pragma unroll
        for (int jp = 0; jp < 4; jp++) {
            uint32_t b0, b1, b2, b3;
            int nrow = (jp * 2 + (mat >> 1)) * 8 + mlow;
            int kc = k0 + (mat & 1) * 8;
            uint32_t addr = s2u(sW + nrow * AST + kc);
            asm volatile(
                "ldmatrix.sync.aligned.m8n8.x4.shared.b16 {%0,%1,%2,%3}, [%4];"
                : "=r"(b0), "=r"(b1), "=r"(b2), "=r"(b3) : "r"(addr));
            int j = jp * 2;
            MMA16816(c0[j], c1[j], c2[j], c3[j], a0, a1, a2, a3, b0, b1);
            MMA16816(c0[j + 1], c1[j + 1], c2[j + 1], c3[j + 1],
                     a0, a1, a2, a3, b2, b3);
        }
    }

    float sa2 = 0.f, sb2 = 0.f;
    #pragma unroll
    for (int j = 0; j < 8; j++) {
        c0[j] = fmaxf(c0[j], 0.f); c1[j] = fmaxf(c1[j], 0.f);
        c2[j] = fmaxf(c2[j], 0.f); c3[j] = fmaxf(c3[j], 0.f);
        sa2 = fmaf(c0[j], c0[j], sa2); sa2 = fmaf(c1[j], c1[j], sa2);
        sb2 = fmaf(c2[j], c2[j], sb2); sb2 = fmaf(c3[j], c3[j], sb2);
    }
    sa2 += __shfl_xor_sync(0xffffffffu, sa2, 1);
    sa2 += __shfl_xor_sync(0xffffffffu, sa2, 2);
    sb2 += __shfl_xor_sync(0xffffffffu, sb2, 1);
    sb2 += __shfl_xor_sync(0xffffffffu, sb2, 2);
    float invA = 1.f / fmaxf(sqrtf(sa2), 1e-12f);
    float invB = 1.f / fmaxf(sqrtf(sb2), 1e-12f);

    int nA = base + m0 + g, nB = nA + 8;
    if (mode == 0) {
        if (nA < nrows) {
            #pragma unroll
            for (int j = 0; j < 8; j++)
                *(__half2*)(hho + (size_t)nA * 64 + j * 8 + 2 * tg) =
                    __floats2half2_rn(c0[j] * invA, c1[j] * invA);
        }
        if (nB < nrows) {
            #pragma unroll
            for (int j = 0; j < 8; j++)
                *(__half2*)(hho + (size_t)nB * 64 + j * 8 + 2 * tg) =
                    __floats2half2_rn(c2[j] * invB, c3[j] * invB);
        }
    } else {
        if (nA < nrows) {
            #pragma unroll
            for (int j = 0; j < 8; j++)
                *(float2*)(out + (size_t)nA * 64 + j * 8 + 2 * tg) =
                    make_float2(c0[j] * invA, c1[j] * invA);
        }
        if (nB < nrows) {
            #pragma unroll
            for (int j = 0; j < 8; j++)
                *(float2*)(out + (size_t)nB * 64 + j * 8 + 2 * tg) =
                    make_float2(c2[j] * invB, c3[j] * invB);
        }
    }
}

// ---------------- batch update (folds NQ quarter-partials) ----------------
__global__ void __launch_bounds__(128) update_hs(
    const float* __restrict__ hs, const float* __restrict__ bl,
    float* __restrict__ out) {
    __shared__ float sWa[4096], sWb[4096];
    __shared__ float sh[2048], shn[2048];
    int t = threadIdx.x;
    int base = blockIdx.x * 32;
    for (int i = t; i < 1024; i += 128) {
        ((float4*)sWa)[i] = ((const float4*)g_Wa)[i];
        ((float4*)sWb)[i] = ((const float4*)g_Wb)[i];
    }
    for (int i = t; i < 512; i += 128)
        ((float4*)sh)[i] = ((const float4*)(hs + base * 64))[i];
    for (int i = t; i < 512; i += 128) {
        float4 s = make_float4(0.f, 0.f, 0.f, 0.f);
        #pragma unroll
        for (int q = 0; q < NQ; q++) {
            float4 v = ((const float4*)g_ppq)[q * 1024 + base * 16 + i];
            s.x += v.x; s.y += v.y; s.z += v.z; s.w += v.w;
        }
        ((float4*)shn)[i] = s;
    }
    __syncthreads();

    int nl = t >> 2, part = t & 3;
    float2 acc[8];
    #pragma unroll
    for (int i = 0; i < 8; i++) acc[i] = ((const float2*)bl)[part * 8 + i];

    const float4* wa4 = (const float4*)sWa;
    const float4* wb4 = (const float4*)sWb;
    const float* hr = sh + nl * 64;
    const float* hnr = shn + nl * 64;

    #pragma unroll 4
    for (int k = 0; k < 64; k++) {
        float a = hr[k], b = hnr[k];
        float2 a2 = make_float2(a, a), b2 = make_float2(b, b);
        #pragma unroll
        for (int i = 0; i < 4; i++) {
            float4 wa = wa4[k * 16 + part * 4 + i];
            ffma2(acc[2 * i],     a2, make_float2(wa.x, wa.y));
            ffma2(acc[2 * i + 1], a2, make_float2(wa.z, wa.w));
            float4 wb = wb4[k * 16 + part * 4 + i];
            ffma2(acc[2 * i],     b2, make_float2(wb.x, wb.y));
            ffma2(acc[2 * i + 1], b2, make_float2(wb.z, wb.w));
        }
    }

    float s = 0.f;
    #pragma unroll
    for (int i = 0; i < 8; i++) {
        acc[i].x = fmaxf(acc[i].x, 0.f);
        acc[i].y = fmaxf(acc[i].y, 0.f);
        s = fmaf(acc[i].x, acc[i].x, s);
        s = fmaf(acc[i].y, acc[i].y, s);
    }
    s += __shfl_xor_sync(0xffffffffu, s, 1);
    s += __shfl_xor_sync(0xffffffffu, s, 2);
    float inv = 1.f / fmaxf(sqrtf(s), 1e-12f);

    float4* o4 = (float4*)(out + (base + nl) * 64 + part * 16);
    #pragma unroll
    for (int i = 0; i < 4; i++)
        o4[i] = make_float4(acc[2 * i].x * inv, acc[2 * i].y * inv,
                            acc[2 * i + 1].x * inv, acc[2 * i + 1].y * inv);
}

// ---------------- host orchestration: dual-stream, triple-buffered hh -----
extern "C" void kernel_launch(void* const* d_in, const int* in_sizes, int n_in,
                              void* d_out, int out_size) {
    const int*   edge_row     = (const int*)d_in[0];
    const int*   edge_col     = (const int*)d_in[1];
    const int*   batch_assign = (const int*)d_in[2];
    const float* X            = (const float*)d_in[3];
    const float* Xs           = (const float*)d_in[4];
    const float* W1           = (const float*)d_in[5];
    const float* W2           = (const float*)d_in[6];
    const float* W3           = (const float*)d_in[7];
    const float* Wl           = (const float*)d_in[8];
    const float* bl           = (const float*)d_in[9];
    float* out = (float*)d_out;

    int nE = in_sizes[0];

    float *hsA, *hsB;
    __half *hh0, *hh1, *hh2, *hnv, *Wt;
    int* rp;
    cudaGetSymbolAddress((void**)&hh0, g_hh0);
    cudaGetSymbolAddress((void**)&hh1, g_hh1);
    cudaGetSymbolAddress((void**)&hh2, g_hh2);
    cudaGetSymbolAddress((void**)&hnv, g_hnv);
    cudaGetSymbolAddress((void**)&hsA, g_hsA);
    cudaGetSymbolAddress((void**)&hsB, g_hsB);
    cudaGetSymbolAddress((void**)&Wt,  g_Wt);
    cudaGetSymbolAddress((void**)&rp,  g_rowptr);
    __half* hhbuf[3] = {hh0, hh1, hh2};

    cudaStream_t s1 = 0;   // capture (legacy) stream: node path
    cudaStream_t s2;       // batch path
    cudaStreamCreateWithFlags(&s2, cudaStreamNonBlocking);
    cudaEvent_t evFork, evEnd, evU[2], evP0;
    cudaEventCreateWithFlags(&evFork, cudaEventDisableTiming);
    cudaEventCreateWithFlags(&evEnd,  cudaEventDisableTiming);
    cudaEventCreateWithFlags(&evU[0], cudaEventDisableTiming);
    cudaEventCreateWithFlags(&evU[1], cudaEventDisableTiming);
    cudaEventCreateWithFlags(&evP0,   cudaEventDisableTiming);

    int prep_blocks = 2 + INIT_BLKS + (nE + 255) / 256;
    prep<<<prep_blocks, 256, 0, s1>>>(edge_row, nE, X, Xs, W1, W2, W3, Wl,
                                      hh0, hsA);
    cudaEventRecord(evFork, s1);
    cudaStreamWaitEvent(s2, evFork, 0);

    float* hsc = hsA; float* hsn = hsB;
    for (int d = 0; d < 3; d++) {
        __half* hhc = hhbuf[d % 3];
        __half* hhn = hhbuf[(d + 1) % 3];
        float*  hsout = (d == 2) ? (out + N_NODES * D_EMB) : hsn;
        int     mode  = (d == 2) ? 1 : 0;

        if (d == 0) {
            // R14 enqueue order: pool first on s2, then node path
            pool_partial<<<PB, 128, 0, s2>>>(hhc, batch_assign, N_NODES);
            cudaEventRecord(evP0, s2);
            spmm<<<(N_NODES * 32 + 255) / 256, 256, 0, s1>>>(
                hhc, edge_col, rp, hnv);
            update_h<<<(NPAD / UH_NODES), 128, 0, s1>>>(
                hhc, hnv, Wt, bl, out, hhn, N_NODES, mode);
            cudaEventRecord(evU[d], s1);
            pool_reduce<<<64, 256, 0, s2>>>();
            update_hs<<<2, 128, 0, s2>>>(hsc, bl, hsout);
        } else {
            cudaStreamWaitEvent(s2, evU[d - 1], 0);   // pool reads h(d)
            spmm<<<(N_NODES * 32 + 255) / 256, 256, 0, s1>>>(
                hhc, edge_col, rp, hnv);
            pool_partial<<<PB, 128, 0, s2>>>(hhc, batch_assign, N_NODES);
            pool_reduce<<<64, 256, 0, s2>>>();
            update_hs<<<2, 128, 0, s2>>>(hsc, bl, hsout);

            // WAR: update_h(2) writes hh0, which pool_partial(0) read
            if (d == 2) cudaStreamWaitEvent(s1, evP0, 0);
            update_h<<<(NPAD / UH_NODES), 128, 0, s1>>>(
                hhc, hnv, Wt, bl, out, hhn, N_NODES, mode);
            if (d < 2) cudaEventRecord(evU[d], s1);
        }

        float* tf = hsc; hsc = hsn; hsn = tf;
    }

    cudaEventRecord(evEnd, s2);
    cudaStreamWaitEvent(s1, evEnd, 0);   // join: all output visible on s1
}